// round 13
// baseline (speedup 1.0000x reference)
#include <cuda_runtime.h>
#include <cuda_fp16.h>
#include <cstdint>

#define NB   16
#define CC   128
#define HH   112
#define WW   112
#define PLANE (HH*WW)          // 12544
#define PTS   25088            // points per image
#define NCHUNK 7
#define CH_SZ  4096            // 6 chunks of 4096 + 1 chunk of 512

// Permuted point records: {b00 | (local_idx<<14), half2(wx,wy)}
__device__ uint2 g_recs[(size_t)NB * PTS];

static __device__ __forceinline__ unsigned int h2u(__half2 h)
{ union { __half2 h; unsigned int u; } c; c.h = h; return c.u; }
static __device__ __forceinline__ __half2 u2h(unsigned int u)
{ union { __half2 h; unsigned int u; } c; c.u = u; return c.h; }
static __device__ __forceinline__ float unn(float v)
{ return fminf(fmaxf(fmaf(v + 1.0f, 56.0f, -0.5f), 0.0f), 111.0f); }

// ---------------- Prepass: build bank-sorted permuted records ----------------
// Per (image, chunk): bucket points into 32x32 cells (gather-bank, idx%32),
// assign warps as diagonal transversals -> each output warp of 32 records has
// distinct gather banks AND distinct idx%32. Shortfall handled by fallback
// matching (any bijection is correct; output values are order-independent).
__global__ __launch_bounds__(512, 1)
void prepass_kernel(const float* __restrict__ grid)
{
    extern __shared__ unsigned int sh[];
    unsigned int* meta = sh;            // [4096] b00 | rank<<14
    unsigned int* wb   = sh + 4096;     // [4096] half2(wx,wy) bits
    unsigned int* sp   = sh + 8192;     // [4096] slot -> point
    unsigned int* cnt  = sh + 12288;    // [1024] cell counts
    unsigned int* lft  = sh + 13312;    // [4096] leftover points
    unsigned int* unf  = sh + 17408;    // [4096] unfilled slots
    unsigned int* ctr  = sh + 21504;    // [2]

    const int n    = blockIdx.x / NCHUNK;
    const int c    = blockIdx.x % NCHUNK;
    const int sz   = (c < 6) ? CH_SZ : (PTS - 6 * CH_SZ);   // 4096 or 512
    const int base = c * CH_SZ;
    const int nW   = sz >> 5;
    const int t    = threadIdx.x;

    for (int i = t; i < 1024; i += 512) cnt[i] = 0;
    if (t < 2) ctr[t] = 0;
    __syncthreads();

    const float2* __restrict__ g2 =
        reinterpret_cast<const float2*>(grid) + (size_t)n * PTS + base;

    for (int j = t; j < sz; j += 512) {
        const float2 xy = g2[j];
        const float x = unn(xy.x), y = unn(xy.y);
        const int x0 = min((int)x, WW - 2);
        const int y0 = min((int)y, HH - 2);
        const float wx = x - (float)x0;
        const float wy = y - (float)y0;
        const unsigned int b00 = (unsigned int)(y0 * WW + x0);
        const unsigned int cell = (b00 & 31) * 32 + (j & 31);
        const unsigned int rank = atomicAdd(&cnt[cell], 1);
        meta[j] = b00 | (rank << 14);
        wb[j]   = h2u(__floats2half2_rn(wx, wy));
    }
    __syncthreads();

    // direct diagonal assignment; leftovers pushed
    for (int j = t; j < sz; j += 512) {
        const unsigned int m = meta[j];
        const int bank = (int)(m & 31);
        const unsigned int rank = m >> 14;
        const int r = j & 31;
        const int d = (r - bank) & 31;
        const unsigned int hits = (d < nW) ? (unsigned int)((nW - d + 31) >> 5) : 0u;
        if (rank < hits)
            sp[(unsigned int)(((d + ((int)rank << 5)) << 5) | bank)] = (unsigned int)j;
        else
            lft[atomicAdd(&ctr[0], 1)] = (unsigned int)j;
    }
    __syncthreads();

    // unfilled slots: round index h has no rank-h point in its cell
    for (int s = t; s < sz; s += 512) {
        const int bank = s & 31;
        const int w = s >> 5;
        const int d = w & 31;
        const int h = w >> 5;
        const int r = (bank + d) & 31;
        if ((unsigned int)h >= cnt[bank * 32 + r])
            unf[atomicAdd(&ctr[1], 1)] = (unsigned int)s;
    }
    __syncthreads();

    const int nU = (int)ctr[1];
    for (int i = t; i < nU; i += 512) sp[unf[i]] = lft[i];
    __syncthreads();

    uint2* __restrict__ ro = g_recs + (size_t)n * PTS + base;
    for (int s = t; s < sz; s += 512) {
        const unsigned int j = sp[s];
        ro[s] = make_uint2((meta[j] & 0x3FFFu) | (j << 14), wb[j]);
    }
}

// ---------------- Main: stage plane, conflict-free gather, drain -------------
__global__ __launch_bounds__(512, 3)
void sample_kernel(const float* __restrict__ fm, float* __restrict__ out)
{
    extern __shared__ unsigned int smem[];
    __half2* plane       = reinterpret_cast<__half2*>(smem);  // [12544]
    unsigned int* stage  = smem + PLANE;                      // [4096]

    const int n  = blockIdx.x >> 6;          // 16 images
    const int c0 = (blockIdx.x & 63) * 2;    // 64 channel pairs
    const int t  = threadIdx.x;

    // stage 2 channel planes packed as half2 (LDG.128 x2 + STS.128)
    {
        const float4* __restrict__ pa =
            reinterpret_cast<const float4*>(fm + ((size_t)n * CC + c0) * PLANE);
        const float4* __restrict__ pb = pa + PLANE / 4;
        uint4* __restrict__ sd = reinterpret_cast<uint4*>(plane);
        #pragma unroll
        for (int i = t; i < PLANE / 4; i += 512) {
            const float4 a = pa[i];
            const float4 b = pb[i];
            uint4 v;
            v.x = h2u(__floats2half2_rn(a.x, b.x));
            v.y = h2u(__floats2half2_rn(a.y, b.y));
            v.z = h2u(__floats2half2_rn(a.z, b.z));
            v.w = h2u(__floats2half2_rn(a.w, b.w));
            sd[i] = v;
        }
    }
    __syncthreads();

    const uint2* __restrict__ rb = g_recs + (size_t)n * PTS;
    float* __restrict__ ob = out + (((size_t)n * 98) * CC + c0) * 256;

    for (int c = 0; c < NCHUNK; c++) {
        const int sz = (c < 6) ? CH_SZ : (PTS - 6 * CH_SZ);
        const uint2* __restrict__ rc = rb + c * CH_SZ;

        // gather phase: warp = 32 consecutive permuted records
        // -> distinct gather banks (conflict-free LDS) and distinct idx%32 (cf STS)
        #pragma unroll 2
        for (int k = t; k < sz; k += 512) {
            const uint2 rec = rc[k];
            const int b00 = (int)(rec.x & 0x3FFFu);
            const int idx = (int)(rec.x >> 14);
            const __half2 w  = u2h(rec.y);
            const __half2 wx2 = __half2half2(__low2half(w));
            const __half2 wy2 = __half2half2(__high2half(w));

            const __half2 q00 = plane[b00];
            const __half2 q01 = plane[b00 + 1];
            const __half2 q10 = plane[b00 + WW];
            const __half2 q11 = plane[b00 + WW + 1];

            const __half2 top = __hfma2(wx2, __hsub2(q01, q00), q00);
            const __half2 bot = __hfma2(wx2, __hsub2(q11, q10), q10);
            stage[idx] = h2u(__hfma2(wy2, __hsub2(bot, top), top));
        }
        __syncthreads();

        // drain phase: coalesced, original pix order
        float* __restrict__ oc = ob + (size_t)(c * 16) * (CC * 256);
        if (sz == CH_SZ) {
            const int j = t * 8;                      // 512*8 = 4096
            const uint4 a = *reinterpret_cast<const uint4*>(stage + j);
            const uint4 b = *reinterpret_cast<const uint4*>(stage + j + 4);
            const float2 f0 = __half22float2(u2h(a.x));
            const float2 f1 = __half22float2(u2h(a.y));
            const float2 f2 = __half22float2(u2h(a.z));
            const float2 f3 = __half22float2(u2h(a.w));
            const float2 f4 = __half22float2(u2h(b.x));
            const float2 f5 = __half22float2(u2h(b.y));
            const float2 f6 = __half22float2(u2h(b.z));
            const float2 f7 = __half22float2(u2h(b.w));
            float* __restrict__ o = oc + (j >> 8) * (CC * 256) + (j & 255);
            *reinterpret_cast<float4*>(o)       = make_float4(f0.x, f1.x, f2.x, f3.x);
            *reinterpret_cast<float4*>(o + 4)   = make_float4(f4.x, f5.x, f6.x, f7.x);
            *reinterpret_cast<float4*>(o + 256) = make_float4(f0.y, f1.y, f2.y, f3.y);
            *reinterpret_cast<float4*>(o + 260) = make_float4(f4.y, f5.y, f6.y, f7.y);
        } else {
            const int j = t;                          // 512 tail points
            const float2 f = __half22float2(u2h(stage[j]));
            float* __restrict__ o = oc + (j >> 8) * (CC * 256) + (j & 255);
            o[0]   = f.x;
            o[256] = f.y;
        }
        __syncthreads();
    }
}

extern "C" void kernel_launch(void* const* d_in, const int* in_sizes, int n_in,
                              void* d_out, int out_size)
{
    const float* fm   = (const float*)d_in[0];   // [16,128,112,112] f32
    const float* grid = (const float*)d_in[1];   // [16,98,16,16,2]  f32
    float* out        = (float*)d_out;           // [16,98,128,16,16] f32

    const int pre_smem  = 21506 * 4;                       // 86,024 B
    const int main_smem = PLANE * 4 + CH_SZ * 4;           // 66,560 B
    cudaFuncSetAttribute(prepass_kernel,
                         cudaFuncAttributeMaxDynamicSharedMemorySize, pre_smem);
    cudaFuncSetAttribute(sample_kernel,
                         cudaFuncAttributeMaxDynamicSharedMemorySize, main_smem);

    prepass_kernel<<<NB * NCHUNK, 512, pre_smem>>>(grid);
    sample_kernel<<<NB * (CC / 2), 512, main_smem>>>(fm, out);
}

// round 14
// speedup vs baseline: 1.0050x; 1.0050x over previous
#include <cuda_runtime.h>
#include <cuda_fp16.h>
#include <cstdint>

#define NB   16
#define CC   128
#define HH   112
#define WW   112
#define PLANE (HH*WW)          // 12544
#define PTS   25088            // points per image
#define NCHUNK 7
#define CH_SZ  4096            // 6 chunks of 4096 + 1 chunk of 512

// Permuted point records: {b00 | (local_idx<<14), half2(wx,wy)}
__device__ uint2 g_recs[(size_t)NB * PTS];

static __device__ __forceinline__ unsigned int h2u(__half2 h)
{ union { __half2 h; unsigned int u; } c; c.h = h; return c.u; }
static __device__ __forceinline__ __half2 u2h(unsigned int u)
{ union { __half2 h; unsigned int u; } c; c.u = u; return c.h; }
static __device__ __forceinline__ float unn(float v)
{ return fminf(fmaxf(fmaf(v + 1.0f, 56.0f, -0.5f), 0.0f), 111.0f); }

// ---------------- Prepass: build bank-sorted permuted records ----------------
// Per (image, chunk): bucket points into 32x32 cells (gather-bank, idx%32),
// assign warps as diagonal transversals -> each output warp of 32 records has
// distinct gather banks AND distinct idx%32. Shortfall handled by fallback
// matching (any bijection is correct; output values are order-independent).
__global__ __launch_bounds__(512, 1)
void prepass_kernel(const float* __restrict__ grid)
{
    extern __shared__ unsigned int sh[];
    unsigned int* meta = sh;            // [4096] b00 | rank<<14
    unsigned int* wb   = sh + 4096;     // [4096] half2(wx,wy) bits
    unsigned int* sp   = sh + 8192;     // [4096] slot -> point
    unsigned int* cnt  = sh + 12288;    // [1024] cell counts
    unsigned int* lft  = sh + 13312;    // [4096] leftover points
    unsigned int* unf  = sh + 17408;    // [4096] unfilled slots
    unsigned int* ctr  = sh + 21504;    // [2]

    const int n    = blockIdx.x / NCHUNK;
    const int c    = blockIdx.x % NCHUNK;
    const int sz   = (c < 6) ? CH_SZ : (PTS - 6 * CH_SZ);   // 4096 or 512
    const int base = c * CH_SZ;
    const int nW   = sz >> 5;
    const int t    = threadIdx.x;

    for (int i = t; i < 1024; i += 512) cnt[i] = 0;
    if (t < 2) ctr[t] = 0;
    __syncthreads();

    const float2* __restrict__ g2 =
        reinterpret_cast<const float2*>(grid) + (size_t)n * PTS + base;

    for (int j = t; j < sz; j += 512) {
        const float2 xy = g2[j];
        const float x = unn(xy.x), y = unn(xy.y);
        const int x0 = min((int)x, WW - 2);
        const int y0 = min((int)y, HH - 2);
        const float wx = x - (float)x0;
        const float wy = y - (float)y0;
        const unsigned int b00 = (unsigned int)(y0 * WW + x0);
        const unsigned int cell = (b00 & 31) * 32 + (j & 31);
        const unsigned int rank = atomicAdd(&cnt[cell], 1);
        meta[j] = b00 | (rank << 14);
        wb[j]   = h2u(__floats2half2_rn(wx, wy));
    }
    __syncthreads();

    // direct diagonal assignment; leftovers pushed
    for (int j = t; j < sz; j += 512) {
        const unsigned int m = meta[j];
        const int bank = (int)(m & 31);
        const unsigned int rank = m >> 14;
        const int r = j & 31;
        const int d = (r - bank) & 31;
        const unsigned int hits = (d < nW) ? (unsigned int)((nW - d + 31) >> 5) : 0u;
        if (rank < hits)
            sp[(unsigned int)(((d + ((int)rank << 5)) << 5) | bank)] = (unsigned int)j;
        else
            lft[atomicAdd(&ctr[0], 1)] = (unsigned int)j;
    }
    __syncthreads();

    // unfilled slots: round index h has no rank-h point in its cell
    for (int s = t; s < sz; s += 512) {
        const int bank = s & 31;
        const int w = s >> 5;
        const int d = w & 31;
        const int h = w >> 5;
        const int r = (bank + d) & 31;
        if ((unsigned int)h >= cnt[bank * 32 + r])
            unf[atomicAdd(&ctr[1], 1)] = (unsigned int)s;
    }
    __syncthreads();

    const int nU = (int)ctr[1];
    for (int i = t; i < nU; i += 512) sp[unf[i]] = lft[i];
    __syncthreads();

    uint2* __restrict__ ro = g_recs + (size_t)n * PTS + base;
    for (int s = t; s < sz; s += 512) {
        const unsigned int j = sp[s];
        ro[s] = make_uint2((meta[j] & 0x3FFFu) | (j << 14), wb[j]);
    }
}

// ---------------- Main: stage plane, conflict-free gather, drain -------------
__global__ __launch_bounds__(512, 3)
void sample_kernel(const float* __restrict__ fm, float* __restrict__ out)
{
    extern __shared__ unsigned int smem[];
    __half2* plane       = reinterpret_cast<__half2*>(smem);  // [12544]
    unsigned int* stage  = smem + PLANE;                      // [4096]

    const int n  = blockIdx.x >> 6;          // 16 images
    const int c0 = (blockIdx.x & 63) * 2;    // 64 channel pairs
    const int t  = threadIdx.x;

    // stage 2 channel planes packed as half2 (LDG.128 x2 + STS.128)
    {
        const float4* __restrict__ pa =
            reinterpret_cast<const float4*>(fm + ((size_t)n * CC + c0) * PLANE);
        const float4* __restrict__ pb = pa + PLANE / 4;
        uint4* __restrict__ sd = reinterpret_cast<uint4*>(plane);
        #pragma unroll
        for (int i = t; i < PLANE / 4; i += 512) {
            const float4 a = pa[i];
            const float4 b = pb[i];
            uint4 v;
            v.x = h2u(__floats2half2_rn(a.x, b.x));
            v.y = h2u(__floats2half2_rn(a.y, b.y));
            v.z = h2u(__floats2half2_rn(a.z, b.z));
            v.w = h2u(__floats2half2_rn(a.w, b.w));
            sd[i] = v;
        }
    }
    __syncthreads();

    const uint2* __restrict__ rb = g_recs + (size_t)n * PTS;
    float* __restrict__ ob = out + (((size_t)n * 98) * CC + c0) * 256;

    for (int c = 0; c < NCHUNK; c++) {
        const int sz = (c < 6) ? CH_SZ : (PTS - 6 * CH_SZ);
        const uint2* __restrict__ rc = rb + c * CH_SZ;

        // gather phase: warp = 32 consecutive permuted records
        // -> distinct gather banks (conflict-free LDS) and distinct idx%32 (cf STS)
        #pragma unroll 2
        for (int k = t; k < sz; k += 512) {
            const uint2 rec = rc[k];
            const int b00 = (int)(rec.x & 0x3FFFu);
            const int idx = (int)(rec.x >> 14);
            const __half2 w  = u2h(rec.y);
            const __half2 wx2 = __half2half2(__low2half(w));
            const __half2 wy2 = __half2half2(__high2half(w));

            const __half2 q00 = plane[b00];
            const __half2 q01 = plane[b00 + 1];
            const __half2 q10 = plane[b00 + WW];
            const __half2 q11 = plane[b00 + WW + 1];

            const __half2 top = __hfma2(wx2, __hsub2(q01, q00), q00);
            const __half2 bot = __hfma2(wx2, __hsub2(q11, q10), q10);
            stage[idx] = h2u(__hfma2(wy2, __hsub2(bot, top), top));
        }
        __syncthreads();

        // drain phase: coalesced, original pix order
        float* __restrict__ oc = ob + (size_t)(c * 16) * (CC * 256);
        if (sz == CH_SZ) {
            const int j = t * 8;                      // 512*8 = 4096
            const uint4 a = *reinterpret_cast<const uint4*>(stage + j);
            const uint4 b = *reinterpret_cast<const uint4*>(stage + j + 4);
            const float2 f0 = __half22float2(u2h(a.x));
            const float2 f1 = __half22float2(u2h(a.y));
            const float2 f2 = __half22float2(u2h(a.z));
            const float2 f3 = __half22float2(u2h(a.w));
            const float2 f4 = __half22float2(u2h(b.x));
            const float2 f5 = __half22float2(u2h(b.y));
            const float2 f6 = __half22float2(u2h(b.z));
            const float2 f7 = __half22float2(u2h(b.w));
            float* __restrict__ o = oc + (j >> 8) * (CC * 256) + (j & 255);
            *reinterpret_cast<float4*>(o)       = make_float4(f0.x, f1.x, f2.x, f3.x);
            *reinterpret_cast<float4*>(o + 4)   = make_float4(f4.x, f5.x, f6.x, f7.x);
            *reinterpret_cast<float4*>(o + 256) = make_float4(f0.y, f1.y, f2.y, f3.y);
            *reinterpret_cast<float4*>(o + 260) = make_float4(f4.y, f5.y, f6.y, f7.y);
        } else {
            const int j = t;                          // 512 tail points
            const float2 f = __half22float2(u2h(stage[j]));
            float* __restrict__ o = oc + (j >> 8) * (CC * 256) + (j & 255);
            o[0]   = f.x;
            o[256] = f.y;
        }
        __syncthreads();
    }
}

extern "C" void kernel_launch(void* const* d_in, const int* in_sizes, int n_in,
                              void* d_out, int out_size)
{
    const float* fm   = (const float*)d_in[0];   // [16,128,112,112] f32
    const float* grid = (const float*)d_in[1];   // [16,98,16,16,2]  f32
    float* out        = (float*)d_out;           // [16,98,128,16,16] f32

    const int pre_smem  = 21506 * 4;                       // 86,024 B
    const int main_smem = PLANE * 4 + CH_SZ * 4;           // 66,560 B
    cudaFuncSetAttribute(prepass_kernel,
                         cudaFuncAttributeMaxDynamicSharedMemorySize, pre_smem);
    cudaFuncSetAttribute(sample_kernel,
                         cudaFuncAttributeMaxDynamicSharedMemorySize, main_smem);

    prepass_kernel<<<NB * NCHUNK, 512, pre_smem>>>(grid);
    sample_kernel<<<NB * (CC / 2), 512, main_smem>>>(fm, out);
}

// round 15
// speedup vs baseline: 1.7415x; 1.7329x over previous
#include <cuda_runtime.h>
#include <cuda_fp16.h>
#include <cstdint>

// Problem constants
#define NB   16
#define CC   128
#define HH   112
#define WW   112
#define PLANE (HH*WW)          // 12544 pixels per plane
#define PTS   (98*16*16)       // 25088 sample points per image
#define THREADS 512
#define HALF_PAIRS 6272        // pairs per half-block (6272 = 12*512 + 128)
#define FULL_ITERS 12
#define TAIL_PAIRS 128

static __device__ __forceinline__ unsigned int h2_bits(__half2 h)
{
    union { __half2 h; unsigned int u; } cvt;
    cvt.h = h;
    return cvt.u;
}

static __device__ __forceinline__ __half2 bilerp_h2(const __half2* __restrict__ s,
                                                    float x, float y)
{
    const int x0 = min((int)x, WW - 2);
    const int y0 = min((int)y, HH - 2);
    const float wx = x - (float)x0;
    const float wy = y - (float)y0;
    const int b00 = y0 * WW + x0;

    const __half2 q00 = s[b00];
    const __half2 q01 = s[b00 + 1];
    const __half2 q10 = s[b00 + WW];
    const __half2 q11 = s[b00 + WW + 1];

    const __half2 wx2 = __float2half2_rn(wx);
    const __half2 wy2 = __float2half2_rn(wy);
    const __half2 top = __hfma2(wx2, __hsub2(q01, q00), q00);
    const __half2 bot = __hfma2(wx2, __hsub2(q11, q10), q10);
    return __hfma2(wy2, __hsub2(bot, top), top);
}

static __device__ __forceinline__ float unnx(float v)
{
    return fminf(fmaxf(fmaf(v + 1.0f, 56.0f, -0.5f), 0.0f), 111.0f);
}

// smem: one half2 per pixel packing channels (c0, c0+1) -> 50,176 B
// 2048 blocks: (image, channel-pair, half-of-points) for fine wave granularity
__global__ __launch_bounds__(THREADS, 3)
void patches_kernel(const float* __restrict__ fm,
                    const float* __restrict__ grid,
                    float* __restrict__ out)
{
    extern __shared__ __half2 s[];   // PLANE half2

    const int blk  = blockIdx.x;
    const int h    = blk & 1;                // which half of the points
    const int tile = blk >> 1;
    const int n    = tile >> 6;              // 16 images
    const int c0   = (tile & 63) * 2;        // 64 channel pairs

    // ---- Stage 2 channel planes packed as half2 (LDG.128 x2 + STS.128) ----
    {
        const float4* __restrict__ pa =
            reinterpret_cast<const float4*>(fm + ((size_t)n * CC + c0) * PLANE);
        const float4* __restrict__ pb = pa + PLANE / 4;     // next channel plane
        uint4* __restrict__ sd = reinterpret_cast<uint4*>(s);
        #pragma unroll
        for (int i = threadIdx.x; i < PLANE / 4; i += THREADS) {
            const float4 a = pa[i];
            const float4 b = pb[i];
            uint4 v;
            v.x = h2_bits(__floats2half2_rn(a.x, b.x));
            v.y = h2_bits(__floats2half2_rn(a.y, b.y));
            v.z = h2_bits(__floats2half2_rn(a.z, b.z));
            v.w = h2_bits(__floats2half2_rn(a.w, b.w));
            sd[i] = v;
        }
    }
    __syncthreads();

    const int t = threadIdx.x;

    // Paired points: pair q covers points 2q, 2q+1 (adjacent pix).
    // This half processes q in [h*6272, h*6272 + 6272).
    const float4* __restrict__ g4 =
        reinterpret_cast<const float4*>(grid) + (size_t)n * (PTS / 2)
        + h * HALF_PAIRS + t;

    // out[n, p, c, hg, wg]  flat = ((n*98 + p)*128 + c)*256 + pix
    // q = h*6272 + i*512 + t -> p = 49h + 4i + (t>>7), pix = (2t)&255
    float* __restrict__ ob = out + (((size_t)n * 98) * CC + c0) * 256;
    float* __restrict__ o = ob + (49 * h + (t >> 7)) * (CC * 256) + ((2 * t) & 255);

    #pragma unroll 4
    for (int i = 0; i < FULL_ITERS; i++) {
        const float4 xy2 = g4[i * THREADS];      // points 2q, 2q+1

        const float xA = unnx(xy2.x), yA = unnx(xy2.y);
        const float xB = unnx(xy2.z), yB = unnx(xy2.w);

        const __half2 rA = bilerp_h2(s, xA, yA);
        const __half2 rB = bilerp_h2(s, xB, yB);

        const float2 fA = __half22float2(rA);
        const float2 fB = __half22float2(rB);

        float* __restrict__ oi = o + i * (4 * CC * 256);
        *reinterpret_cast<float2*>(oi)       = make_float2(fA.x, fB.x);
        *reinterpret_cast<float2*>(oi + 256) = make_float2(fA.y, fB.y);
    }

    // Tail: 128 pairs, q = h*6272 + 6144 + t (t < 128)
    if (t < TAIL_PAIRS) {
        const float4 xy2 = g4[FULL_ITERS * THREADS];

        const float xA = unnx(xy2.x), yA = unnx(xy2.y);
        const float xB = unnx(xy2.z), yB = unnx(xy2.w);

        const __half2 rA = bilerp_h2(s, xA, yA);
        const __half2 rB = bilerp_h2(s, xB, yB);

        const float2 fA = __half22float2(rA);
        const float2 fB = __half22float2(rB);

        // p = 49h + 48, pix = 2t
        float* __restrict__ ot = ob + (49 * h + 48) * (CC * 256) + 2 * t;
        *reinterpret_cast<float2*>(ot)       = make_float2(fA.x, fB.x);
        *reinterpret_cast<float2*>(ot + 256) = make_float2(fA.y, fB.y);
    }
}

extern "C" void kernel_launch(void* const* d_in, const int* in_sizes, int n_in,
                              void* d_out, int out_size)
{
    const float* fm   = (const float*)d_in[0];   // [16,128,112,112] f32
    const float* grid = (const float*)d_in[1];   // [16,98,16,16,2]  f32
    float* out        = (float*)d_out;           // [16,98,128,16,16] f32

    const int smem = PLANE * sizeof(__half2);    // 50,176 B
    cudaFuncSetAttribute(patches_kernel,
                         cudaFuncAttributeMaxDynamicSharedMemorySize, smem);

    const int blocks = NB * (CC / 2) * 2;        // 2048
    patches_kernel<<<blocks, THREADS, smem>>>(fm, grid, out);
}